// round 1
// baseline (speedup 1.0000x reference)
#include <cuda_runtime.h>

// Problem constants
#define BB 2
#define TT 2048
#define DD 1024
#define HH 16
#define HDIM 64
#define MROWS (BB * TT)   // 4096
#define N_QKV (3 * DD)    // 3072

// Scratch (device globals: no allocation allowed)
__device__ float g_Q[BB * HH * TT * HDIM];
__device__ float g_K[BB * HH * TT * HDIM];
__device__ float g_V[BB * HH * TT * HDIM];
__device__ float g_Y[BB * TT * DD];

// ---------------------------------------------------------------------------
// GEMM 1: qkv = x @ Wqkv + bqkv, scattered into Q/K/V [B,H,T,HD]
// BM=128, BN=128, BK=16, 256 threads, 8x8 per thread
// ---------------------------------------------------------------------------
__global__ __launch_bounds__(256) void qkv_gemm_kernel(
    const float* __restrict__ A,      // x  [4096,1024]
    const float* __restrict__ Bm,     // Wqkv [1024,3072]
    const float* __restrict__ bias)   // bqkv [3072]
{
    __shared__ float Ast[16][128];    // A transposed: Ast[k][m]
    __shared__ float Bs[16][128];

    const int tid = threadIdx.x;
    const int tx = tid & 15;          // col group (8 cols)
    const int ty = tid >> 4;          // row group (8 rows)
    const int m0 = blockIdx.y * 128;
    const int n0 = blockIdx.x * 128;

    float acc[8][8];
#pragma unroll
    for (int i = 0; i < 8; i++)
#pragma unroll
        for (int j = 0; j < 8; j++) acc[i][j] = 0.f;

    for (int kt = 0; kt < DD / 16; ++kt) {
        // Load A tile (128x16) transposed into Ast
#pragma unroll
        for (int r = 0; r < 2; ++r) {
            int f = tid + 256 * r;         // 512 float4s
            int row = f >> 2, c4 = f & 3;
            float4 v = *(const float4*)&A[(size_t)(m0 + row) * DD + kt * 16 + c4 * 4];
            Ast[c4 * 4 + 0][row] = v.x;
            Ast[c4 * 4 + 1][row] = v.y;
            Ast[c4 * 4 + 2][row] = v.z;
            Ast[c4 * 4 + 3][row] = v.w;
        }
        // Load B tile (16x128)
#pragma unroll
        for (int r = 0; r < 2; ++r) {
            int f = tid + 256 * r;
            int k = f >> 5, c4 = f & 31;
            *(float4*)&Bs[k][c4 * 4] =
                *(const float4*)&Bm[(size_t)(kt * 16 + k) * N_QKV + n0 + c4 * 4];
        }
        __syncthreads();

#pragma unroll
        for (int k = 0; k < 16; ++k) {
            float4 a0 = *(float4*)&Ast[k][ty * 8];
            float4 a1 = *(float4*)&Ast[k][ty * 8 + 4];
            float4 b0 = *(float4*)&Bs[k][tx * 8];
            float4 b1 = *(float4*)&Bs[k][tx * 8 + 4];
            float a[8] = {a0.x, a0.y, a0.z, a0.w, a1.x, a1.y, a1.z, a1.w};
            float b[8] = {b0.x, b0.y, b0.z, b0.w, b1.x, b1.y, b1.z, b1.w};
#pragma unroll
            for (int i = 0; i < 8; i++)
#pragma unroll
                for (int j = 0; j < 8; j++)
                    acc[i][j] = fmaf(a[i], b[j], acc[i][j]);
        }
        __syncthreads();
    }

    // Epilogue: add bias, scatter to Q/K/V in [B,H,T,HD]
#pragma unroll
    for (int i = 0; i < 8; i++) {
        int m = m0 + ty * 8 + i;
        int b = m >> 11;              // / 2048
        int t = m & 2047;
#pragma unroll
        for (int j = 0; j < 8; j++) {
            int n = n0 + tx * 8 + j;
            float v = acc[i][j] + bias[n];
            int three = n >> 10;          // /1024
            int h = (n >> 6) & 15;
            int hd = n & 63;
            size_t idx = ((size_t)(b * HH + h) * TT + t) * HDIM + hd;
            if (three == 0) g_Q[idx] = v;
            else if (three == 1) g_K[idx] = v;
            else g_V[idx] = v;
        }
    }
}

// ---------------------------------------------------------------------------
// Flash attention (fp32, causal): per-(b,h) 64-query tile blocks
// 128 threads: tx = tid&7 (8 col groups x 8), ty = tid>>3 (16 row groups x 4)
// Row stats held redundantly in the 8 lanes sharing a row group (shfl-reduced).
// P^T aliases the K smem buffer -> exactly 48KB static smem.
// ---------------------------------------------------------------------------
__device__ __forceinline__ float redmax8(float v) {
    v = fmaxf(v, __shfl_xor_sync(0xffffffffu, v, 1));
    v = fmaxf(v, __shfl_xor_sync(0xffffffffu, v, 2));
    v = fmaxf(v, __shfl_xor_sync(0xffffffffu, v, 4));
    return v;
}
__device__ __forceinline__ float redsum8(float v) {
    v += __shfl_xor_sync(0xffffffffu, v, 1);
    v += __shfl_xor_sync(0xffffffffu, v, 2);
    v += __shfl_xor_sync(0xffffffffu, v, 4);
    return v;
}

__global__ __launch_bounds__(128) void attn_kernel() {
    __shared__ float Qts[64][64];    // Q^T:  Qts[d][row], pre-scaled
    __shared__ float KtsP[64][64];   // K^T:  KtsP[d][col]; later P^T: KtsP[j][row]
    __shared__ float Vs[64][64];     // V:    Vs[j][d]

    const int tid = threadIdx.x;
    const int tx = tid & 7;          // col group: cols tx*8 .. tx*8+7
    const int ty = tid >> 3;         // row group: rows ty*4 .. ty*4+3
    const int qt = blockIdx.x;       // query tile (0..31)
    const int bh = blockIdx.y;       // b*H + h   (0..31)

    const float* Qg = g_Q + (size_t)bh * TT * HDIM;
    const float* Kg = g_K + (size_t)bh * TT * HDIM;
    const float* Vg = g_V + (size_t)bh * TT * HDIM;
    const float scale = 0.125f;      // HD^-0.5

    // Load Q tile transposed, pre-scaled
#pragma unroll
    for (int r = 0; r < 8; ++r) {
        int f = tid + 128 * r;       // 1024 float4s
        int row = f >> 4, c4 = f & 15;
        float4 v = *(const float4*)&Qg[(size_t)(qt * 64 + row) * HDIM + c4 * 4];
        Qts[c4 * 4 + 0][row] = v.x * scale;
        Qts[c4 * 4 + 1][row] = v.y * scale;
        Qts[c4 * 4 + 2][row] = v.z * scale;
        Qts[c4 * 4 + 3][row] = v.w * scale;
    }

    float o[4][8];
#pragma unroll
    for (int i = 0; i < 4; i++)
#pragma unroll
        for (int j = 0; j < 8; j++) o[i][j] = 0.f;
    float mi[4] = {-1e30f, -1e30f, -1e30f, -1e30f};
    float li[4] = {0.f, 0.f, 0.f, 0.f};

    for (int kt = 0; kt <= qt; ++kt) {
        __syncthreads();   // prior-tile P/V reads done (and Q load on first iter)
        // Load K (transposed) and V tiles
#pragma unroll
        for (int r = 0; r < 8; ++r) {
            int f = tid + 128 * r;
            int row = f >> 4, c4 = f & 15;
            size_t gidx = (size_t)(kt * 64 + row) * HDIM + c4 * 4;
            float4 kv = *(const float4*)&Kg[gidx];
            KtsP[c4 * 4 + 0][row] = kv.x;
            KtsP[c4 * 4 + 1][row] = kv.y;
            KtsP[c4 * 4 + 2][row] = kv.z;
            KtsP[c4 * 4 + 3][row] = kv.w;
            *(float4*)&Vs[row][c4 * 4] = *(const float4*)&Vg[gidx];
        }
        __syncthreads();

        // S = Q @ K^T  (64x64), micro-tile 4x8
        float s[4][8];
#pragma unroll
        for (int i = 0; i < 4; i++)
#pragma unroll
            for (int j = 0; j < 8; j++) s[i][j] = 0.f;

#pragma unroll 8
        for (int d = 0; d < 64; ++d) {
            float4 aq = *(float4*)&Qts[d][ty * 4];
            float4 b0 = *(float4*)&KtsP[d][tx * 8];
            float4 b1 = *(float4*)&KtsP[d][tx * 8 + 4];
            float a[4] = {aq.x, aq.y, aq.z, aq.w};
            float b[8] = {b0.x, b0.y, b0.z, b0.w, b1.x, b1.y, b1.z, b1.w};
#pragma unroll
            for (int i = 0; i < 4; i++)
#pragma unroll
                for (int j = 0; j < 8; j++)
                    s[i][j] = fmaf(a[i], b[j], s[i][j]);
        }
        __syncthreads();   // all K^T reads done; smem reusable as P^T

        // causal mask on diagonal tile
        if (kt == qt) {
#pragma unroll
            for (int i = 0; i < 4; i++) {
                int gq = ty * 4 + i;
#pragma unroll
                for (int j = 0; j < 8; j++) {
                    if (tx * 8 + j > gq) s[i][j] = -1e30f;
                }
            }
        }

        // online softmax update (per row group; 8 lanes share rows)
        float alpha[4];
#pragma unroll
        for (int i = 0; i < 4; i++) {
            float pm = s[i][0];
#pragma unroll
            for (int j = 1; j < 8; j++) pm = fmaxf(pm, s[i][j]);
            pm = redmax8(pm);
            float mn = fmaxf(mi[i], pm);
            alpha[i] = __expf(mi[i] - mn);
            float ps = 0.f;
#pragma unroll
            for (int j = 0; j < 8; j++) {
                s[i][j] = __expf(s[i][j] - mn);
                ps += s[i][j];
            }
            ps = redsum8(ps);
            li[i] = li[i] * alpha[i] + ps;
            mi[i] = mn;
        }

        // write P^T into aliased buffer; rescale O
#pragma unroll
        for (int i = 0; i < 4; i++) {
#pragma unroll
            for (int j = 0; j < 8; j++)
                KtsP[tx * 8 + j][ty * 4 + i] = s[i][j];
#pragma unroll
            for (int d = 0; d < 8; d++) o[i][d] *= alpha[i];
        }
        __syncthreads();

        // O += P @ V
#pragma unroll 8
        for (int j = 0; j < 64; ++j) {
            float4 ap = *(float4*)&KtsP[j][ty * 4];
            float4 b0 = *(float4*)&Vs[j][tx * 8];
            float4 b1 = *(float4*)&Vs[j][tx * 8 + 4];
            float a[4] = {ap.x, ap.y, ap.z, ap.w};
            float b[8] = {b0.x, b0.y, b0.z, b0.w, b1.x, b1.y, b1.z, b1.w};
#pragma unroll
            for (int i = 0; i < 4; i++)
#pragma unroll
                for (int d = 0; d < 8; d++)
                    o[i][d] = fmaf(a[i], b[d], o[i][d]);
        }
    }

    // normalize + write to g_Y in [B, T, D] layout (D index = h*64 + d)
    const int b = bh >> 4;
    const int h = bh & 15;
#pragma unroll
    for (int i = 0; i < 4; i++) {
        float inv = 1.f / li[i];
        int t = qt * 64 + ty * 4 + i;
        float* dst = &g_Y[((size_t)(b * TT + t)) * DD + h * HDIM + tx * 8];
#pragma unroll
        for (int d = 0; d < 8; d++) dst[d] = o[i][d] * inv;
    }
}

// ---------------------------------------------------------------------------
// GEMM 2: out = g_Y @ Wout + bout   (4096x1024x1024) -> d_out
// ---------------------------------------------------------------------------
__global__ __launch_bounds__(256) void out_gemm_kernel(
    const float* __restrict__ Bm,     // Wout [1024,1024]
    const float* __restrict__ bias,   // bout [1024]
    float* __restrict__ out)
{
    __shared__ float Ast[16][128];
    __shared__ float Bs[16][128];

    const int tid = threadIdx.x;
    const int tx = tid & 15;
    const int ty = tid >> 4;
    const int m0 = blockIdx.y * 128;
    const int n0 = blockIdx.x * 128;
    const float* A = g_Y;

    float acc[8][8];
#pragma unroll
    for (int i = 0; i < 8; i++)
#pragma unroll
        for (int j = 0; j < 8; j++) acc[i][j] = 0.f;

    for (int kt = 0; kt < DD / 16; ++kt) {
#pragma unroll
        for (int r = 0; r < 2; ++r) {
            int f = tid + 256 * r;
            int row = f >> 2, c4 = f & 3;
            float4 v = *(const float4*)&A[(size_t)(m0 + row) * DD + kt * 16 + c4 * 4];
            Ast[c4 * 4 + 0][row] = v.x;
            Ast[c4 * 4 + 1][row] = v.y;
            Ast[c4 * 4 + 2][row] = v.z;
            Ast[c4 * 4 + 3][row] = v.w;
        }
#pragma unroll
        for (int r = 0; r < 2; ++r) {
            int f = tid + 256 * r;
            int k = f >> 5, c4 = f & 31;
            *(float4*)&Bs[k][c4 * 4] =
                *(const float4*)&Bm[(size_t)(kt * 16 + k) * DD + n0 + c4 * 4];
        }
        __syncthreads();

#pragma unroll
        for (int k = 0; k < 16; ++k) {
            float4 a0 = *(float4*)&Ast[k][ty * 8];
            float4 a1 = *(float4*)&Ast[k][ty * 8 + 4];
            float4 b0 = *(float4*)&Bs[k][tx * 8];
            float4 b1 = *(float4*)&Bs[k][tx * 8 + 4];
            float a[8] = {a0.x, a0.y, a0.z, a0.w, a1.x, a1.y, a1.z, a1.w};
            float b[8] = {b0.x, b0.y, b0.z, b0.w, b1.x, b1.y, b1.z, b1.w};
#pragma unroll
            for (int i = 0; i < 8; i++)
#pragma unroll
                for (int j = 0; j < 8; j++)
                    acc[i][j] = fmaf(a[i], b[j], acc[i][j]);
        }
        __syncthreads();
    }

#pragma unroll
    for (int i = 0; i < 8; i++) {
        int m = m0 + ty * 8 + i;
#pragma unroll
        for (int j = 0; j < 8; j++) {
            int n = n0 + tx * 8 + j;
            out[(size_t)m * DD + n] = acc[i][j] + bias[n];
        }
    }
}

// ---------------------------------------------------------------------------
extern "C" void kernel_launch(void* const* d_in, const int* in_sizes, int n_in,
                              void* d_out, int out_size) {
    const float* x    = (const float*)d_in[0];
    const float* Wqkv = (const float*)d_in[1];
    const float* bqkv = (const float*)d_in[2];
    const float* Wout = (const float*)d_in[3];
    const float* bout = (const float*)d_in[4];
    float* out = (float*)d_out;

    // 1) QKV projection + head-split scatter
    {
        dim3 grid(N_QKV / 128, MROWS / 128);   // 24 x 32
        qkv_gemm_kernel<<<grid, 256>>>(x, Wqkv, bqkv);
    }
    // 2) causal flash attention per (b,h,q-tile)
    {
        dim3 grid(TT / 64, BB * HH);           // 32 x 32
        attn_kernel<<<grid, 128>>>();
    }
    // 3) output projection
    {
        dim3 grid(DD / 128, MROWS / 128);      // 8 x 32
        out_gemm_kernel<<<grid, 256>>>(Wout, bout, out);
    }
}

// round 14
// speedup vs baseline: 2.1788x; 2.1788x over previous
#include <cuda_runtime.h>
#include <cuda_bf16.h>
#include <cstdint>

// ---------------------------------------------------------------------------
// Problem constants
// ---------------------------------------------------------------------------
#define BB 2
#define TT 2048
#define DD 1024
#define HH 16
#define HDIM 64
#define MROWS (BB * TT)   // 4096
#define N_QKV (3 * DD)    // 3072
#define GK DD             // inner K of both projections = 1024

// ---------------------------------------------------------------------------
// Device scratch — ONLY referenced inside device code (never passed from host!)
// ---------------------------------------------------------------------------
__device__ float g_Q[BB * HH * TT * HDIM];
__device__ float g_K[BB * HH * TT * HDIM];
__device__ float g_V[BB * HH * TT * HDIM];
__device__ __nv_bfloat16 g_Xh[MROWS * DD];
__device__ __nv_bfloat16 g_Xl[MROWS * DD];
__device__ __nv_bfloat16 g_Wqh[N_QKV * DD];   // Wqkv^T hi  [3072,1024]
__device__ __nv_bfloat16 g_Wql[N_QKV * DD];
__device__ __nv_bfloat16 g_Woh[DD * DD];      // Wout^T hi  [1024,1024]
__device__ __nv_bfloat16 g_Wol[DD * DD];
__device__ __nv_bfloat16 g_Yh[MROWS * DD];
__device__ __nv_bfloat16 g_Yl[MROWS * DD];

// ---------------------------------------------------------------------------
// Kernel: fp32 -> bf16 hi/lo split of x (direct device refs for outputs)
// ---------------------------------------------------------------------------
__global__ __launch_bounds__(256) void xconv_kernel(const float* __restrict__ x) {
    int i = (blockIdx.x * 256 + threadIdx.x) * 8;
    float4 a = *(const float4*)(x + i);
    float4 b = *(const float4*)(x + i + 4);
    float v[8] = {a.x, a.y, a.z, a.w, b.x, b.y, b.z, b.w};
    __align__(16) __nv_bfloat16 hi[8];
    __align__(16) __nv_bfloat16 lo[8];
#pragma unroll
    for (int j = 0; j < 8; j++) {
        hi[j] = __float2bfloat16(v[j]);
        lo[j] = __float2bfloat16(v[j] - __bfloat162float(hi[j]));
    }
    *(uint4*)&g_Xh[i] = *(uint4*)hi;
    *(uint4*)&g_Xl[i] = *(uint4*)lo;
}

// ---------------------------------------------------------------------------
// Kernel: transpose + hi/lo split of W[K=1024, N] -> Wt[N, 1024]
// WSEL 0: write g_Wqh/g_Wql (Ncols=3072); WSEL 1: write g_Woh/g_Wol (Ncols=1024)
// ---------------------------------------------------------------------------
template <int WSEL>
__global__ __launch_bounds__(256) void wconv_kernel(const float* __restrict__ W) {
    const int Ncols = (WSEL == 0) ? N_QKV : DD;
    __nv_bfloat16* Wh = (WSEL == 0) ? g_Wqh : g_Woh;
    __nv_bfloat16* Wl = (WSEL == 0) ? g_Wql : g_Wol;

    __shared__ float ts[32][33];
    const int n0 = blockIdx.x * 32;
    const int k0 = blockIdx.y * 32;
    const int tx = threadIdx.x & 31;
    const int ty = threadIdx.x >> 5;   // 0..7
#pragma unroll
    for (int i = 0; i < 32; i += 8)
        ts[ty + i][tx] = W[(size_t)(k0 + ty + i) * Ncols + n0 + tx];
    __syncthreads();
#pragma unroll
    for (int i = 0; i < 32; i += 8) {
        float v = ts[tx][ty + i];              // W[k0+tx][n0+ty+i]
        __nv_bfloat16 h = __float2bfloat16(v);
        __nv_bfloat16 l = __float2bfloat16(v - __bfloat162float(h));
        size_t idx = (size_t)(n0 + ty + i) * GK + k0 + tx;
        Wh[idx] = h;
        Wl[idx] = l;
    }
}

// ---------------------------------------------------------------------------
// Raw mma.sync bf16x3 GEMM: C[128x128 tile] = A @ B^T (+bias)
// Sources are device globals selected by MODE (device-side refs only).
// MODE 0: A=g_Xh/g_Xl, B=g_Wqh/g_Wql, scatter fp32 -> g_Q/g_K/g_V [B,H,T,HD]
// MODE 1: A=g_Yh/g_Yl, B=g_Woh/g_Wol, write fp32 Cout[m*DD+n]
// 256 threads = 8 warps in 4(M) x 2(N); warp tile 32x64 via m16n8k16.
// ---------------------------------------------------------------------------
#define BK 32
#define LDT 40
#define TILE_ELEMS (128 * LDT)

__device__ __forceinline__ void mma_bf16(float* d, const uint32_t* a,
                                         const uint32_t* b) {
    asm volatile(
        "mma.sync.aligned.m16n8k16.row.col.f32.bf16.bf16.f32 "
        "{%0,%1,%2,%3}, {%4,%5,%6,%7}, {%8,%9}, {%0,%1,%2,%3};\n"
        : "+f"(d[0]), "+f"(d[1]), "+f"(d[2]), "+f"(d[3])
        : "r"(a[0]), "r"(a[1]), "r"(a[2]), "r"(a[3]), "r"(b[0]), "r"(b[1]));
}

template <int MODE>
__global__ __launch_bounds__(256) void mm_gemm_kernel(
    const float* __restrict__ bias,
    float* __restrict__ Cout) {
    __shared__ __align__(16) __nv_bfloat16 sm[4 * TILE_ELEMS];  // 40 KB
    __nv_bfloat16* sAh = sm;
    __nv_bfloat16* sAl = sm + TILE_ELEMS;
    __nv_bfloat16* sBh = sm + 2 * TILE_ELEMS;
    __nv_bfloat16* sBl = sm + 3 * TILE_ELEMS;

    const int tid = threadIdx.x;
    const int wid = tid >> 5;
    const int lane = tid & 31;
    const int g = lane >> 2;
    const int t = lane & 3;
    const int warp_m = wid >> 1;
    const int warp_n = wid & 1;
    const int m0 = blockIdx.y * 128;
    const int n0 = blockIdx.x * 128;

    // Device-side global references (the R7/R9/R12 bug was passing these from host)
    const __nv_bfloat16* ahg = ((MODE == 0) ? g_Xh : g_Yh) + (size_t)m0 * GK;
    const __nv_bfloat16* alg = ((MODE == 0) ? g_Xl : g_Yl) + (size_t)m0 * GK;
    const __nv_bfloat16* bhg = ((MODE == 0) ? g_Wqh : g_Woh) + (size_t)n0 * GK;
    const __nv_bfloat16* blg = ((MODE == 0) ? g_Wql : g_Wol) + (size_t)n0 * GK;

    float acc[2][8][4];
#pragma unroll
    for (int i = 0; i < 2; i++)
#pragma unroll
        for (int j = 0; j < 8; j++)
#pragma unroll
            for (int c = 0; c < 4; c++) acc[i][j][c] = 0.f;

    for (int kt = 0; kt < GK / BK; ++kt) {
#pragma unroll
        for (int r = 0; r < 2; ++r) {
            int e = tid + 256 * r;
            int row = e >> 2, c = e & 3;
            size_t gofs = (size_t)row * GK + kt * BK + c * 8;
            int sofs = row * LDT + c * 8;
            *(uint4*)&sAh[sofs] = *(const uint4*)&ahg[gofs];
            *(uint4*)&sAl[sofs] = *(const uint4*)&alg[gofs];
            *(uint4*)&sBh[sofs] = *(const uint4*)&bhg[gofs];
            *(uint4*)&sBl[sofs] = *(const uint4*)&blg[gofs];
        }
        __syncthreads();

#pragma unroll
        for (int ks = 0; ks < BK; ks += 16) {
            uint32_t ah[2][4], al[2][4];
#pragma unroll
            for (int mt = 0; mt < 2; mt++) {
                const __nv_bfloat16* pA =
                    &sAh[(warp_m * 32 + mt * 16 + g) * LDT + ks + 2 * t];
                ah[mt][0] = *(const uint32_t*)pA;
                ah[mt][1] = *(const uint32_t*)(pA + 8 * LDT);
                ah[mt][2] = *(const uint32_t*)(pA + 8);
                ah[mt][3] = *(const uint32_t*)(pA + 8 * LDT + 8);
                const __nv_bfloat16* pAl =
                    &sAl[(warp_m * 32 + mt * 16 + g) * LDT + ks + 2 * t];
                al[mt][0] = *(const uint32_t*)pAl;
                al[mt][1] = *(const uint32_t*)(pAl + 8 * LDT);
                al[mt][2] = *(const uint32_t*)(pAl + 8);
                al[mt][3] = *(const uint32_t*)(pAl + 8 * LDT + 8);
            }
#pragma unroll
            for (int nt = 0; nt < 8; nt++) {
                uint32_t bh[2], bl[2];
                const __nv_bfloat16* pB =
                    &sBh[(warp_n * 64 + nt * 8 + g) * LDT + ks + 2 * t];
                bh[0] = *(const uint32_t*)pB;
                bh[1] = *(const uint32_t*)(pB + 8);
                const __nv_bfloat16* pBl =
                    &sBl[(warp_n * 64 + nt * 8 + g) * LDT + ks + 2 * t];
                bl[0] = *(const uint32_t*)pBl;
                bl[1] = *(const uint32_t*)(pBl + 8);
#pragma unroll
                for (int mt = 0; mt < 2; mt++) {
                    mma_bf16(acc[mt][nt], ah[mt], bh);
                    mma_bf16(acc[mt][nt], ah[mt], bl);
                    mma_bf16(acc[mt][nt], al[mt], bh);
                }
            }
        }
        __syncthreads();
    }

    // Epilogue: two 128x64 halves staged through smem (reuses tile smem)
    float* epi = (float*)sm;
#pragma unroll
    for (int hf = 0; hf < 2; ++hf) {
        if (warp_n == hf) {
#pragma unroll
            for (int mt = 0; mt < 2; mt++)
#pragma unroll
                for (int nt = 0; nt < 8; nt++) {
                    int row = warp_m * 32 + mt * 16 + g;
                    int col = nt * 8 + 2 * t;
                    epi[row * 68 + col]           = acc[mt][nt][0];
                    epi[row * 68 + col + 1]       = acc[mt][nt][1];
                    epi[(row + 8) * 68 + col]     = acc[mt][nt][2];
                    epi[(row + 8) * 68 + col + 1] = acc[mt][nt][3];
                }
        }
        __syncthreads();
#pragma unroll
        for (int r = 0; r < 8; ++r) {
            int e = tid + 256 * r;
            int row = e >> 4, c4 = e & 15;
            int n = n0 + hf * 64 + c4 * 4;
            float4 v;
            v.x = epi[row * 68 + c4 * 4 + 0] + bias[n + 0];
            v.y = epi[row * 68 + c4 * 4 + 1] + bias[n + 1];
            v.z = epi[row * 68 + c4 * 4 + 2] + bias[n + 2];
            v.w = epi[row * 68 + c4 * 4 + 3] + bias[n + 3];
            int m = m0 + row;
            if (MODE == 0) {
                int b = m >> 11, tt_ = m & 2047;
                int three = n >> 10;
                int h = (n >> 6) & 15;
                int hd = n & 63;
                float* dst = (three == 0) ? g_Q : (three == 1) ? g_K : g_V;
                *(float4*)&dst[((size_t)(b * HH + h) * TT + tt_) * HDIM + hd] = v;
            } else {
                *(float4*)&Cout[(size_t)m * DD + n] = v;
            }
        }
        __syncthreads();
    }
}

// ---------------------------------------------------------------------------
// Flash attention (fp32, causal) — proven kernel; epilogue emits bf16 hi/lo Y
// ---------------------------------------------------------------------------
__device__ __forceinline__ float redmax8(float v) {
    v = fmaxf(v, __shfl_xor_sync(0xffffffffu, v, 1));
    v = fmaxf(v, __shfl_xor_sync(0xffffffffu, v, 2));
    v = fmaxf(v, __shfl_xor_sync(0xffffffffu, v, 4));
    return v;
}
__device__ __forceinline__ float redsum8(float v) {
    v += __shfl_xor_sync(0xffffffffu, v, 1);
    v += __shfl_xor_sync(0xffffffffu, v, 2);
    v += __shfl_xor_sync(0xffffffffu, v, 4);
    return v;
}

__global__ __launch_bounds__(128) void attn_kernel() {
    __shared__ float Qts[64][64];
    __shared__ float KtsP[64][64];
    __shared__ float Vs[64][64];

    const int tid = threadIdx.x;
    const int tx = tid & 7;
    const int ty = tid >> 3;
    const int qt = gridDim.x - 1 - blockIdx.x;   // long blocks first
    const int bh = blockIdx.y;

    const float* Qg = g_Q + (size_t)bh * TT * HDIM;
    const float* Kg = g_K + (size_t)bh * TT * HDIM;
    const float* Vg = g_V + (size_t)bh * TT * HDIM;
    const float scale = 0.125f;

#pragma unroll
    for (int r = 0; r < 8; ++r) {
        int f = tid + 128 * r;
        int row = f >> 4, c4 = f & 15;
        float4 v = *(const float4*)&Qg[(size_t)(qt * 64 + row) * HDIM + c4 * 4];
        Qts[c4 * 4 + 0][row] = v.x * scale;
        Qts[c4 * 4 + 1][row] = v.y * scale;
        Qts[c4 * 4 + 2][row] = v.z * scale;
        Qts[c4 * 4 + 3][row] = v.w * scale;
    }

    float o[4][8];
#pragma unroll
    for (int i = 0; i < 4; i++)
#pragma unroll
        for (int j = 0; j < 8; j++) o[i][j] = 0.f;
    float mi[4] = {-1e30f, -1e30f, -1e30f, -1e30f};
    float li[4] = {0.f, 0.f, 0.f, 0.f};

    for (int kt = 0; kt <= qt; ++kt) {
        __syncthreads();
#pragma unroll
        for (int r = 0; r < 8; ++r) {
            int f = tid + 128 * r;
            int row = f >> 4, c4 = f & 15;
            size_t gidx = (size_t)(kt * 64 + row) * HDIM + c4 * 4;
            float4 kv = *(const float4*)&Kg[gidx];
            KtsP[c4 * 4 + 0][row] = kv.x;
            KtsP[c4 * 4 + 1][row] = kv.y;
            KtsP[c4 * 4 + 2][row] = kv.z;
            KtsP[c4 * 4 + 3][row] = kv.w;
            *(float4*)&Vs[row][c4 * 4] = *(const float4*)&Vg[gidx];
        }
        __syncthreads();

        float s[4][8];
#pragma unroll
        for (int i = 0; i < 4; i++)
#pragma unroll
            for (int j = 0; j < 8; j++) s[i][j] = 0.f;

#pragma unroll 8
        for (int d = 0; d < 64; ++d) {
            float4 aq = *(float4*)&Qts[d][ty * 4];
            float4 b0 = *(float4*)&KtsP[d][tx * 8];
            float4 b1 = *(float4*)&KtsP[d][tx * 8 + 4];
            float a[4] = {aq.x, aq.y, aq.z, aq.w};
            float b[8] = {b0.x, b0.y, b0.z, b0.w, b1.x, b1.y, b1.z, b1.w};
#pragma unroll
            for (int i = 0; i < 4; i++)
#pragma unroll
                for (int j = 0; j < 8; j++)
                    s[i][j] = fmaf(a[i], b[j], s[i][j]);
        }
        __syncthreads();

        if (kt == qt) {
#pragma unroll
            for (int i = 0; i < 4; i++) {
                int gq = ty * 4 + i;
#pragma unroll
                for (int j = 0; j < 8; j++)
                    if (tx * 8 + j > gq) s[i][j] = -1e30f;
            }
        }

        float alpha[4];
#pragma unroll
        for (int i = 0; i < 4; i++) {
            float pm = s[i][0];
#pragma unroll
            for (int j = 1; j < 8; j++) pm = fmaxf(pm, s[i][j]);
            pm = redmax8(pm);
            float mn = fmaxf(mi[i], pm);
            alpha[i] = __expf(mi[i] - mn);
            float ps = 0.f;
#pragma unroll
            for (int j = 0; j < 8; j++) {
                s[i][j] = __expf(s[i][j] - mn);
                ps += s[i][j];
            }
            ps = redsum8(ps);
            li[i] = li[i] * alpha[i] + ps;
            mi[i] = mn;
        }

#pragma unroll
        for (int i = 0; i < 4; i++) {
#pragma unroll
            for (int j = 0; j < 8; j++)
                KtsP[tx * 8 + j][ty * 4 + i] = s[i][j];
#pragma unroll
            for (int d = 0; d < 8; d++) o[i][d] *= alpha[i];
        }
        __syncthreads();

#pragma unroll 8
        for (int j = 0; j < 64; ++j) {
            float4 ap = *(float4*)&KtsP[j][ty * 4];
            float4 b0 = *(float4*)&Vs[j][tx * 8];
            float4 b1 = *(float4*)&Vs[j][tx * 8 + 4];
            float a[4] = {ap.x, ap.y, ap.z, ap.w};
            float b[8] = {b0.x, b0.y, b0.z, b0.w, b1.x, b1.y, b1.z, b1.w};
#pragma unroll
            for (int i = 0; i < 4; i++)
#pragma unroll
                for (int d = 0; d < 8; d++)
                    o[i][d] = fmaf(a[i], b[d], o[i][d]);
        }
    }

    // epilogue: Y -> bf16 hi/lo in [B,T,D] layout (col = h*64 + d)
    const int b = bh >> 4;
    const int h = bh & 15;
#pragma unroll
    for (int i = 0; i < 4; i++) {
        float inv = 1.f / li[i];
        int t = qt * 64 + ty * 4 + i;
        size_t idx = ((size_t)(b * TT + t)) * DD + h * HDIM + tx * 8;
        __align__(16) __nv_bfloat16 hv[8];
        __align__(16) __nv_bfloat16 lv[8];
#pragma unroll
        for (int d = 0; d < 8; d++) {
            float y = o[i][d] * inv;
            hv[d] = __float2bfloat16(y);
            lv[d] = __float2bfloat16(y - __bfloat162float(hv[d]));
        }
        *(uint4*)&g_Yh[idx] = *(uint4*)hv;
        *(uint4*)&g_Yl[idx] = *(uint4*)lv;
    }
}

// ---------------------------------------------------------------------------
extern "C" void kernel_launch(void* const* d_in, const int* in_sizes, int n_in,
                              void* d_out, int out_size) {
    const float* x    = (const float*)d_in[0];
    const float* Wqkv = (const float*)d_in[1];
    const float* bqkv = (const float*)d_in[2];
    const float* Wout = (const float*)d_in[3];
    const float* bout = (const float*)d_in[4];
    float* out = (float*)d_out;

    // 1) conversions (outputs written via device-side global refs only)
    xconv_kernel<<<MROWS * DD / (256 * 8), 256>>>(x);
    wconv_kernel<0><<<dim3(N_QKV / 32, GK / 32), 256>>>(Wqkv);
    wconv_kernel<1><<<dim3(DD / 32, GK / 32), 256>>>(Wout);

    // 2) QKV projection on tensor cores (bf16x3 raw mma), scatter epilogue
    mm_gemm_kernel<0><<<dim3(N_QKV / 128, MROWS / 128), 256>>>(bqkv, nullptr);

    // 3) causal flash attention (proven fp32 SIMT), emits bf16 hi/lo Y
    attn_kernel<<<dim3(TT / 64, BB * HH), 128>>>();

    // 4) output projection on tensor cores
    mm_gemm_kernel<1><<<dim3(DD / 128, MROWS / 128), 256>>>(bout, out);
}

// round 15
// speedup vs baseline: 4.5836x; 2.1037x over previous
#include <cuda_runtime.h>
#include <cuda_bf16.h>
#include <cstdint>

// ---------------------------------------------------------------------------
// Problem constants
// ---------------------------------------------------------------------------
#define BB 2
#define TT 2048
#define DD 1024
#define HH 16
#define HDIM 64
#define MROWS (BB * TT)   // 4096
#define N_QKV (3 * DD)    // 3072
#define GK DD             // inner K of both projections = 1024

// ---------------------------------------------------------------------------
// Device scratch — ONLY referenced inside device code (never passed from host!)
// ---------------------------------------------------------------------------
__device__ __nv_bfloat16 g_Qh[BB * HH * TT * HDIM];  // pre-scaled by 0.125
__device__ __nv_bfloat16 g_Ql[BB * HH * TT * HDIM];
__device__ __nv_bfloat16 g_Kh[BB * HH * TT * HDIM];
__device__ __nv_bfloat16 g_Kl[BB * HH * TT * HDIM];
__device__ __nv_bfloat16 g_Vh[BB * HH * TT * HDIM];
__device__ __nv_bfloat16 g_Vl[BB * HH * TT * HDIM];
__device__ __nv_bfloat16 g_Vth[BB * HH * HDIM * TT]; // V^T [B,H,HD,T]
__device__ __nv_bfloat16 g_Vtl[BB * HH * HDIM * TT];
__device__ __nv_bfloat16 g_Xh[MROWS * DD];
__device__ __nv_bfloat16 g_Xl[MROWS * DD];
__device__ __nv_bfloat16 g_Wqh[N_QKV * DD];
__device__ __nv_bfloat16 g_Wql[N_QKV * DD];
__device__ __nv_bfloat16 g_Woh[DD * DD];
__device__ __nv_bfloat16 g_Wol[DD * DD];
__device__ __nv_bfloat16 g_Yh[MROWS * DD];
__device__ __nv_bfloat16 g_Yl[MROWS * DD];

// ---------------------------------------------------------------------------
// Helpers
// ---------------------------------------------------------------------------
__device__ __forceinline__ uint32_t pack_bf16x2(float a, float b) {
    __nv_bfloat16 ha = __float2bfloat16(a);
    __nv_bfloat16 hb = __float2bfloat16(b);
    return (uint32_t)__bfloat16_as_ushort(ha) |
           ((uint32_t)__bfloat16_as_ushort(hb) << 16);
}
// split a,b into hi pair (returned) and lo pair (out param)
__device__ __forceinline__ uint32_t split_bf16x2(float a, float b, uint32_t& lo) {
    __nv_bfloat16 ha = __float2bfloat16(a);
    __nv_bfloat16 hb = __float2bfloat16(b);
    float ra = a - __bfloat162float(ha);
    float rb = b - __bfloat162float(hb);
    lo = pack_bf16x2(ra, rb);
    return (uint32_t)__bfloat16_as_ushort(ha) |
           ((uint32_t)__bfloat16_as_ushort(hb) << 16);
}

__device__ __forceinline__ void mma_bf16(float* d, const uint32_t* a,
                                         const uint32_t* b) {
    asm volatile(
        "mma.sync.aligned.m16n8k16.row.col.f32.bf16.bf16.f32 "
        "{%0,%1,%2,%3}, {%4,%5,%6,%7}, {%8,%9}, {%0,%1,%2,%3};\n"
        : "+f"(d[0]), "+f"(d[1]), "+f"(d[2]), "+f"(d[3])
        : "r"(a[0]), "r"(a[1]), "r"(a[2]), "r"(a[3]), "r"(b[0]), "r"(b[1]));
}

// ---------------------------------------------------------------------------
// fp32 -> bf16 hi/lo split of x
// ---------------------------------------------------------------------------
__global__ __launch_bounds__(256) void xconv_kernel(const float* __restrict__ x) {
    int i = (blockIdx.x * 256 + threadIdx.x) * 8;
    float4 a = *(const float4*)(x + i);
    float4 b = *(const float4*)(x + i + 4);
    float v[8] = {a.x, a.y, a.z, a.w, b.x, b.y, b.z, b.w};
    __align__(16) __nv_bfloat16 hi[8];
    __align__(16) __nv_bfloat16 lo[8];
#pragma unroll
    for (int j = 0; j < 8; j++) {
        hi[j] = __float2bfloat16(v[j]);
        lo[j] = __float2bfloat16(v[j] - __bfloat162float(hi[j]));
    }
    *(uint4*)&g_Xh[i] = *(uint4*)hi;
    *(uint4*)&g_Xl[i] = *(uint4*)lo;
}

// ---------------------------------------------------------------------------
// transpose + hi/lo split of W[K=1024, N] -> Wt[N, 1024]
// ---------------------------------------------------------------------------
template <int WSEL>
__global__ __launch_bounds__(256) void wconv_kernel(const float* __restrict__ W) {
    const int Ncols = (WSEL == 0) ? N_QKV : DD;
    __nv_bfloat16* Wh = (WSEL == 0) ? g_Wqh : g_Woh;
    __nv_bfloat16* Wl = (WSEL == 0) ? g_Wql : g_Wol;

    __shared__ float ts[32][33];
    const int n0 = blockIdx.x * 32;
    const int k0 = blockIdx.y * 32;
    const int tx = threadIdx.x & 31;
    const int ty = threadIdx.x >> 5;
#pragma unroll
    for (int i = 0; i < 32; i += 8)
        ts[ty + i][tx] = W[(size_t)(k0 + ty + i) * Ncols + n0 + tx];
    __syncthreads();
#pragma unroll
    for (int i = 0; i < 32; i += 8) {
        float v = ts[tx][ty + i];
        __nv_bfloat16 h = __float2bfloat16(v);
        __nv_bfloat16 l = __float2bfloat16(v - __bfloat162float(h));
        size_t idx = (size_t)(n0 + ty + i) * GK + k0 + tx;
        Wh[idx] = h;
        Wl[idx] = l;
    }
}

// ---------------------------------------------------------------------------
// Raw mma.sync bf16x3 GEMM (both projections)
// MODE 0: A=X, B=Wqkv^T -> scatter bf16 hi/lo Q(scaled)/K/V [B,H,T,HD]
// MODE 1: A=Y, B=Wout^T -> fp32 Cout[m*DD+n]
// ---------------------------------------------------------------------------
#define BK 32
#define LDT 40
#define TILE_ELEMS (128 * LDT)

template <int MODE>
__global__ __launch_bounds__(256) void mm_gemm_kernel(
    const float* __restrict__ bias,
    float* __restrict__ Cout) {
    __shared__ __align__(16) __nv_bfloat16 sm[4 * TILE_ELEMS];  // 40 KB
    __nv_bfloat16* sAh = sm;
    __nv_bfloat16* sAl = sm + TILE_ELEMS;
    __nv_bfloat16* sBh = sm + 2 * TILE_ELEMS;
    __nv_bfloat16* sBl = sm + 3 * TILE_ELEMS;

    const int tid = threadIdx.x;
    const int wid = tid >> 5;
    const int lane = tid & 31;
    const int g = lane >> 2;
    const int t = lane & 3;
    const int warp_m = wid >> 1;
    const int warp_n = wid & 1;
    const int m0 = blockIdx.y * 128;
    const int n0 = blockIdx.x * 128;

    const __nv_bfloat16* ahg = ((MODE == 0) ? g_Xh : g_Yh) + (size_t)m0 * GK;
    const __nv_bfloat16* alg = ((MODE == 0) ? g_Xl : g_Yl) + (size_t)m0 * GK;
    const __nv_bfloat16* bhg = ((MODE == 0) ? g_Wqh : g_Woh) + (size_t)n0 * GK;
    const __nv_bfloat16* blg = ((MODE == 0) ? g_Wql : g_Wol) + (size_t)n0 * GK;

    float acc[2][8][4];
#pragma unroll
    for (int i = 0; i < 2; i++)
#pragma unroll
        for (int j = 0; j < 8; j++)
#pragma unroll
            for (int c = 0; c < 4; c++) acc[i][j][c] = 0.f;

    for (int kt = 0; kt < GK / BK; ++kt) {
#pragma unroll
        for (int r = 0; r < 2; ++r) {
            int e = tid + 256 * r;
            int row = e >> 2, c = e & 3;
            size_t gofs = (size_t)row * GK + kt * BK + c * 8;
            int sofs = row * LDT + c * 8;
            *(uint4*)&sAh[sofs] = *(const uint4*)&ahg[gofs];
            *(uint4*)&sAl[sofs] = *(const uint4*)&alg[gofs];
            *(uint4*)&sBh[sofs] = *(const uint4*)&bhg[gofs];
            *(uint4*)&sBl[sofs] = *(const uint4*)&blg[gofs];
        }
        __syncthreads();

#pragma unroll
        for (int ks = 0; ks < BK; ks += 16) {
            uint32_t ah[2][4], al[2][4];
#pragma unroll
            for (int mt = 0; mt < 2; mt++) {
                const __nv_bfloat16* pA =
                    &sAh[(warp_m * 32 + mt * 16 + g) * LDT + ks + 2 * t];
                ah[mt][0] = *(const uint32_t*)pA;
                ah[mt][1] = *(const uint32_t*)(pA + 8 * LDT);
                ah[mt][2] = *(const uint32_t*)(pA + 8);
                ah[mt][3] = *(const uint32_t*)(pA + 8 * LDT + 8);
                const __nv_bfloat16* pAl =
                    &sAl[(warp_m * 32 + mt * 16 + g) * LDT + ks + 2 * t];
                al[mt][0] = *(const uint32_t*)pAl;
                al[mt][1] = *(const uint32_t*)(pAl + 8 * LDT);
                al[mt][2] = *(const uint32_t*)(pAl + 8);
                al[mt][3] = *(const uint32_t*)(pAl + 8 * LDT + 8);
            }
#pragma unroll
            for (int nt = 0; nt < 8; nt++) {
                uint32_t bh[2], bl[2];
                const __nv_bfloat16* pB =
                    &sBh[(warp_n * 64 + nt * 8 + g) * LDT + ks + 2 * t];
                bh[0] = *(const uint32_t*)pB;
                bh[1] = *(const uint32_t*)(pB + 8);
                const __nv_bfloat16* pBl =
                    &sBl[(warp_n * 64 + nt * 8 + g) * LDT + ks + 2 * t];
                bl[0] = *(const uint32_t*)pBl;
                bl[1] = *(const uint32_t*)(pBl + 8);
#pragma unroll
                for (int mt = 0; mt < 2; mt++) {
                    mma_bf16(acc[mt][nt], ah[mt], bh);
                    mma_bf16(acc[mt][nt], ah[mt], bl);
                    mma_bf16(acc[mt][nt], al[mt], bh);
                }
            }
        }
        __syncthreads();
    }

    // Epilogue staged through smem
    float* epi = (float*)sm;
#pragma unroll
    for (int hf = 0; hf < 2; ++hf) {
        if (warp_n == hf) {
#pragma unroll
            for (int mt = 0; mt < 2; mt++)
#pragma unroll
                for (int nt = 0; nt < 8; nt++) {
                    int row = warp_m * 32 + mt * 16 + g;
                    int col = nt * 8 + 2 * t;
                    epi[row * 68 + col]           = acc[mt][nt][0];
                    epi[row * 68 + col + 1]       = acc[mt][nt][1];
                    epi[(row + 8) * 68 + col]     = acc[mt][nt][2];
                    epi[(row + 8) * 68 + col + 1] = acc[mt][nt][3];
                }
        }
        __syncthreads();
#pragma unroll
        for (int r = 0; r < 8; ++r) {
            int e = tid + 256 * r;
            int row = e >> 4, c4 = e & 15;
            int n = n0 + hf * 64 + c4 * 4;
            float vv[4];
#pragma unroll
            for (int j = 0; j < 4; j++)
                vv[j] = epi[row * 68 + c4 * 4 + j] + bias[n + j];
            int m = m0 + row;
            if (MODE == 0) {
                int b = m >> 11, tt_ = m & 2047;
                int three = n >> 10;
                int h = (n >> 6) & 15;
                int hd = n & 63;
                if (three == 0) {
#pragma unroll
                    for (int j = 0; j < 4; j++) vv[j] *= 0.125f;  // HD^-0.5
                }
                __nv_bfloat16* dsth = (three == 0) ? g_Qh : (three == 1) ? g_Kh : g_Vh;
                __nv_bfloat16* dstl = (three == 0) ? g_Ql : (three == 1) ? g_Kl : g_Vl;
                size_t idx = ((size_t)(b * HH + h) * TT + tt_) * HDIM + hd;
                uint32_t h01, l01, h23, l23;
                h01 = split_bf16x2(vv[0], vv[1], l01);
                h23 = split_bf16x2(vv[2], vv[3], l23);
                uint2 ph = {h01, h23}, pl = {l01, l23};
                *(uint2*)&dsth[idx] = ph;
                *(uint2*)&dstl[idx] = pl;
            } else {
                float4 v = {vv[0], vv[1], vv[2], vv[3]};
                *(float4*)&Cout[(size_t)m * DD + n] = v;
            }
        }
        __syncthreads();
    }
}

// ---------------------------------------------------------------------------
// V transpose: g_Vh/g_Vl [B,H,T,HD] -> g_Vth/g_Vtl [B,H,HD,T]
// ---------------------------------------------------------------------------
__global__ __launch_bounds__(256) void vtrans_kernel() {
    __shared__ __nv_bfloat16 sTh[64][72];
    __shared__ __nv_bfloat16 sTl[64][72];
    const int tid = threadIdx.x;
    const int t0 = blockIdx.x * 64;
    const int bh = blockIdx.y;
    const __nv_bfloat16* Vh = g_Vh + (size_t)bh * TT * HDIM;
    const __nv_bfloat16* Vl = g_Vl + (size_t)bh * TT * HDIM;
#pragma unroll
    for (int r = 0; r < 2; ++r) {
        int e = tid + 256 * r;
        int row = e >> 3, c = e & 7;
        __align__(16) __nv_bfloat16 vh[8], vl[8];
        *(uint4*)vh = *(const uint4*)&Vh[(size_t)(t0 + row) * HDIM + c * 8];
        *(uint4*)vl = *(const uint4*)&Vl[(size_t)(t0 + row) * HDIM + c * 8];
#pragma unroll
        for (int j = 0; j < 8; j++) {
            sTh[c * 8 + j][row] = vh[j];
            sTl[c * 8 + j][row] = vl[j];
        }
    }
    __syncthreads();
#pragma unroll
    for (int r = 0; r < 2; ++r) {
        int e = tid + 256 * r;
        int hd = e >> 3, c = e & 7;
        size_t idx = (size_t)bh * HDIM * TT + (size_t)hd * TT + t0 + c * 8;
        *(uint4*)&g_Vth[idx] = *(uint4*)&sTh[hd][c * 8];
        *(uint4*)&g_Vtl[idx] = *(uint4*)&sTl[hd][c * 8];
    }
}

// ---------------------------------------------------------------------------
// Flash attention on tensor cores (bf16x3), causal.
// CTA: 128 q-rows, 8 warps x 16 rows. K-tiles of 64.
// ---------------------------------------------------------------------------
__global__ __launch_bounds__(256, 1) void fattn_kernel() {
    __shared__ __nv_bfloat16 sKh[64][72];
    __shared__ __nv_bfloat16 sKl[64][72];
    __shared__ __nv_bfloat16 sVh[64][72];   // V^T tile: [hd][key]
    __shared__ __nv_bfloat16 sVl[64][72];

    const int tid = threadIdx.x;
    const int wid = tid >> 5;
    const int lane = tid & 31;
    const int g = lane >> 2;
    const int t = lane & 3;
    const int qt = gridDim.x - 1 - blockIdx.x;   // long blocks first
    const int bh = blockIdx.y;

    const int row0 = qt * 128 + wid * 16 + g;    // t-coordinate of frag row g
    const __nv_bfloat16* Qh = g_Qh + (size_t)bh * TT * HDIM;
    const __nv_bfloat16* Ql = g_Ql + (size_t)bh * TT * HDIM;
    const __nv_bfloat16* Kh = g_Kh + (size_t)bh * TT * HDIM;
    const __nv_bfloat16* Kl = g_Kl + (size_t)bh * TT * HDIM;
    const __nv_bfloat16* Vth = g_Vth + (size_t)bh * HDIM * TT;
    const __nv_bfloat16* Vtl = g_Vtl + (size_t)bh * HDIM * TT;

    // Q fragments, resident for the whole kernel (pre-scaled by 0.125)
    uint32_t qh[4][4], ql[4][4];
#pragma unroll
    for (int kk = 0; kk < 4; kk++) {
        const __nv_bfloat16* p = Qh + (size_t)row0 * HDIM + kk * 16 + 2 * t;
        qh[kk][0] = *(const uint32_t*)p;
        qh[kk][1] = *(const uint32_t*)(p + 8 * HDIM);
        qh[kk][2] = *(const uint32_t*)(p + 8);
        qh[kk][3] = *(const uint32_t*)(p + 8 * HDIM + 8);
        const __nv_bfloat16* pl = Ql + (size_t)row0 * HDIM + kk * 16 + 2 * t;
        ql[kk][0] = *(const uint32_t*)pl;
        ql[kk][1] = *(const uint32_t*)(pl + 8 * HDIM);
        ql[kk][2] = *(const uint32_t*)(pl + 8);
        ql[kk][3] = *(const uint32_t*)(pl + 8 * HDIM + 8);
    }

    float o[8][4];
#pragma unroll
    for (int nt = 0; nt < 8; nt++)
#pragma unroll
        for (int c = 0; c < 4; c++) o[nt][c] = 0.f;
    float mi[2] = {-1e30f, -1e30f};
    float li[2] = {0.f, 0.f};

    const int nkt = 2 * qt + 2;
    const int warp_max_row = qt * 128 + wid * 16 + 15;

    for (int kt = 0; kt < nkt; ++kt) {
        __syncthreads();
        // load K (hi/lo) and V^T (hi/lo) tiles: 4 x 512 uint4
#pragma unroll
        for (int r = 0; r < 2; ++r) {
            int e = tid + 256 * r;
            int row = e >> 3, c = e & 7;
            size_t kofs = (size_t)(kt * 64 + row) * HDIM + c * 8;
            *(uint4*)&sKh[row][c * 8] = *(const uint4*)&Kh[kofs];
            *(uint4*)&sKl[row][c * 8] = *(const uint4*)&Kl[kofs];
            size_t vofs = (size_t)row * TT + kt * 64 + c * 8;
            *(uint4*)&sVh[row][c * 8] = *(const uint4*)&Vth[vofs];
            *(uint4*)&sVl[row][c * 8] = *(const uint4*)&Vtl[vofs];
        }
        __syncthreads();

        if (kt * 64 > warp_max_row) continue;   // fully masked warp tile

        // S = Q @ K^T  (16 x 64 per warp), bf16x3
        float s[8][4];
#pragma unroll
        for (int nt = 0; nt < 8; nt++)
#pragma unroll
            for (int c = 0; c < 4; c++) s[nt][c] = 0.f;
#pragma unroll
        for (int kk = 0; kk < 4; kk++) {
#pragma unroll
            for (int nt = 0; nt < 8; nt++) {
                uint32_t bhf[2], blf[2];
                const __nv_bfloat16* pB = &sKh[nt * 8 + g][kk * 16 + 2 * t];
                bhf[0] = *(const uint32_t*)pB;
                bhf[1] = *(const uint32_t*)(pB + 8);
                const __nv_bfloat16* pBl = &sKl[nt * 8 + g][kk * 16 + 2 * t];
                blf[0] = *(const uint32_t*)pBl;
                blf[1] = *(const uint32_t*)(pBl + 8);
                mma_bf16(s[nt], qh[kk], bhf);
                mma_bf16(s[nt], qh[kk], blf);
                mma_bf16(s[nt], ql[kk], bhf);
            }
        }

        // causal mask (only the last two tiles can touch the diagonal)
        if (kt >= 2 * qt) {
#pragma unroll
            for (int nt = 0; nt < 8; nt++) {
#pragma unroll
                for (int c = 0; c < 4; c++) {
                    int col = kt * 64 + nt * 8 + 2 * t + (c & 1);
                    int row = row0 + ((c >> 1) << 3);
                    if (col > row) s[nt][c] = -1e30f;
                }
            }
        }

        // online softmax per half (rows g and g+8)
        float alpha[2];
#pragma unroll
        for (int hf = 0; hf < 2; hf++) {
            float pm = -1e30f;
#pragma unroll
            for (int nt = 0; nt < 8; nt++)
                pm = fmaxf(pm, fmaxf(s[nt][hf * 2], s[nt][hf * 2 + 1]));
            pm = fmaxf(pm, __shfl_xor_sync(0xffffffffu, pm, 1));
            pm = fmaxf(pm, __shfl_xor_sync(0xffffffffu, pm, 2));
            float mn = fmaxf(mi[hf], pm);
            alpha[hf] = __expf(mi[hf] - mn);
            float ps = 0.f;
#pragma unroll
            for (int nt = 0; nt < 8; nt++) {
                s[nt][hf * 2]     = __expf(s[nt][hf * 2] - mn);
                s[nt][hf * 2 + 1] = __expf(s[nt][hf * 2 + 1] - mn);
                ps += s[nt][hf * 2] + s[nt][hf * 2 + 1];
            }
            ps += __shfl_xor_sync(0xffffffffu, ps, 1);
            ps += __shfl_xor_sync(0xffffffffu, ps, 2);
            li[hf] = li[hf] * alpha[hf] + ps;
            mi[hf] = mn;
        }
#pragma unroll
        for (int nt = 0; nt < 8; nt++) {
            o[nt][0] *= alpha[0];
            o[nt][1] *= alpha[0];
            o[nt][2] *= alpha[1];
            o[nt][3] *= alpha[1];
        }

        // O += P @ V  (P frags come straight from S d-frags; bf16x3)
#pragma unroll
        for (int kk2 = 0; kk2 < 4; kk2++) {
            uint32_t ph[4], plo[4];
            ph[0] = split_bf16x2(s[2 * kk2][0],     s[2 * kk2][1],     plo[0]);
            ph[1] = split_bf16x2(s[2 * kk2][2],     s[2 * kk2][3],     plo[1]);
            ph[2] = split_bf16x2(s[2 * kk2 + 1][0], s[2 * kk2 + 1][1], plo[2]);
            ph[3] = split_bf16x2(s[2 * kk2 + 1][2], s[2 * kk2 + 1][3], plo[3]);
#pragma unroll
            for (int nt = 0; nt < 8; nt++) {
                uint32_t vhf[2], vlf[2];
                const __nv_bfloat16* pV = &sVh[nt * 8 + g][kk2 * 16 + 2 * t];
                vhf[0] = *(const uint32_t*)pV;
                vhf[1] = *(const uint32_t*)(pV + 8);
                const __nv_bfloat16* pVl = &sVl[nt * 8 + g][kk2 * 16 + 2 * t];
                vlf[0] = *(const uint32_t*)pVl;
                vlf[1] = *(const uint32_t*)(pVl + 8);
                mma_bf16(o[nt], ph, vhf);
                mma_bf16(o[nt], ph, vlf);
                mma_bf16(o[nt], plo, vhf);
            }
        }
    }

    // epilogue: normalize, write bf16 hi/lo Y at [B,T,D] (col = h*64 + hd)
    const float inv0 = 1.f / li[0];
    const float inv1 = 1.f / li[1];
    const int b = bh >> 4;
    const int h = bh & 15;
    size_t base0 = ((size_t)(b * TT + row0)) * DD + h * 64;
    size_t base1 = base0 + (size_t)8 * DD;
#pragma unroll
    for (int nt = 0; nt < 8; nt++) {
        int col = nt * 8 + 2 * t;
        uint32_t l0, l1;
        uint32_t h0 = split_bf16x2(o[nt][0] * inv0, o[nt][1] * inv0, l0);
        uint32_t h1 = split_bf16x2(o[nt][2] * inv1, o[nt][3] * inv1, l1);
        *(uint32_t*)&g_Yh[base0 + col] = h0;
        *(uint32_t*)&g_Yl[base0 + col] = l0;
        *(uint32_t*)&g_Yh[base1 + col] = h1;
        *(uint32_t*)&g_Yl[base1 + col] = l1;
    }
}

// ---------------------------------------------------------------------------
extern "C" void kernel_launch(void* const* d_in, const int* in_sizes, int n_in,
                              void* d_out, int out_size) {
    const float* x    = (const float*)d_in[0];
    const float* Wqkv = (const float*)d_in[1];
    const float* bqkv = (const float*)d_in[2];
    const float* Wout = (const float*)d_in[3];
    const float* bout = (const float*)d_in[4];
    float* out = (float*)d_out;

    // 1) conversions
    xconv_kernel<<<MROWS * DD / (256 * 8), 256>>>(x);
    wconv_kernel<0><<<dim3(N_QKV / 32, GK / 32), 256>>>(Wqkv);
    wconv_kernel<1><<<dim3(DD / 32, GK / 32), 256>>>(Wout);

    // 2) QKV projection (bf16x3 mma) -> bf16 hi/lo Q(scaled)/K/V
    mm_gemm_kernel<0><<<dim3(N_QKV / 128, MROWS / 128), 256>>>(bqkv, nullptr);

    // 3) V transpose for the P@V operand
    vtrans_kernel<<<dim3(TT / 64, BB * HH), 256>>>();

    // 4) causal flash attention on tensor cores
    fattn_kernel<<<dim3(TT / 128, BB * HH), 256>>>();

    // 5) output projection (bf16x3 mma)
    mm_gemm_kernel<1><<<dim3(DD / 128, MROWS / 128), 256>>>(bout, out);
}

// round 16
// speedup vs baseline: 4.6293x; 1.0100x over previous
#include <cuda_runtime.h>
#include <cuda_bf16.h>
#include <cstdint>

// ---------------------------------------------------------------------------
// Problem constants
// ---------------------------------------------------------------------------
#define BB 2
#define TT 2048
#define DD 1024
#define HH 16
#define HDIM 64
#define MROWS (BB * TT)   // 4096
#define N_QKV (3 * DD)    // 3072
#define GK DD             // inner K of both projections = 1024

// ---------------------------------------------------------------------------
// Device scratch — ONLY referenced inside device code (never passed from host!)
// ---------------------------------------------------------------------------
__device__ __nv_bfloat16 g_Qh[BB * HH * TT * HDIM];  // pre-scaled by 0.125
__device__ __nv_bfloat16 g_Ql[BB * HH * TT * HDIM];
__device__ __nv_bfloat16 g_Kh[BB * HH * TT * HDIM];
__device__ __nv_bfloat16 g_Kl[BB * HH * TT * HDIM];
__device__ __nv_bfloat16 g_Vh[BB * HH * TT * HDIM];
__device__ __nv_bfloat16 g_Vl[BB * HH * TT * HDIM];
__device__ __nv_bfloat16 g_Vth[BB * HH * HDIM * TT]; // V^T [B,H,HD,T]
__device__ __nv_bfloat16 g_Vtl[BB * HH * HDIM * TT];
__device__ __nv_bfloat16 g_Xh[MROWS * DD];
__device__ __nv_bfloat16 g_Xl[MROWS * DD];
__device__ __nv_bfloat16 g_Wqh[N_QKV * DD];
__device__ __nv_bfloat16 g_Wql[N_QKV * DD];
__device__ __nv_bfloat16 g_Woh[DD * DD];
__device__ __nv_bfloat16 g_Wol[DD * DD];
__device__ __nv_bfloat16 g_Yh[MROWS * DD];
__device__ __nv_bfloat16 g_Yl[MROWS * DD];

// ---------------------------------------------------------------------------
// Helpers
// ---------------------------------------------------------------------------
__device__ __forceinline__ uint32_t smem_u32(const void* p) {
    return (uint32_t)__cvta_generic_to_shared(p);
}
__device__ __forceinline__ uint32_t pack_bf16x2(float a, float b) {
    __nv_bfloat16 ha = __float2bfloat16(a);
    __nv_bfloat16 hb = __float2bfloat16(b);
    return (uint32_t)__bfloat16_as_ushort(ha) |
           ((uint32_t)__bfloat16_as_ushort(hb) << 16);
}
__device__ __forceinline__ uint32_t split_bf16x2(float a, float b, uint32_t& lo) {
    __nv_bfloat16 ha = __float2bfloat16(a);
    __nv_bfloat16 hb = __float2bfloat16(b);
    float ra = a - __bfloat162float(ha);
    float rb = b - __bfloat162float(hb);
    lo = pack_bf16x2(ra, rb);
    return (uint32_t)__bfloat16_as_ushort(ha) |
           ((uint32_t)__bfloat16_as_ushort(hb) << 16);
}
__device__ __forceinline__ void mma_bf16(float* d, const uint32_t* a,
                                         const uint32_t* b) {
    asm volatile(
        "mma.sync.aligned.m16n8k16.row.col.f32.bf16.bf16.f32 "
        "{%0,%1,%2,%3}, {%4,%5,%6,%7}, {%8,%9}, {%0,%1,%2,%3};\n"
        : "+f"(d[0]), "+f"(d[1]), "+f"(d[2]), "+f"(d[3])
        : "r"(a[0]), "r"(a[1]), "r"(a[2]), "r"(a[3]), "r"(b[0]), "r"(b[1]));
}
__device__ __forceinline__ void ldsm_x4(uint32_t* r, uint32_t addr) {
    asm volatile("ldmatrix.sync.aligned.m8n8.x4.shared.b16 {%0,%1,%2,%3}, [%4];"
                 : "=r"(r[0]), "=r"(r[1]), "=r"(r[2]), "=r"(r[3]) : "r"(addr));
}
__device__ __forceinline__ void cp16(uint32_t s, const void* g) {
    asm volatile("cp.async.cg.shared.global [%0], [%1], 16;" :: "r"(s), "l"(g));
}
#define CP_COMMIT() asm volatile("cp.async.commit_group;" ::: "memory")
#define CP_WAIT(N)  asm volatile("cp.async.wait_group %0;" :: "n"(N) : "memory")

// ---------------------------------------------------------------------------
// fp32 -> bf16 hi/lo split of x
// ---------------------------------------------------------------------------
__global__ __launch_bounds__(256) void xconv_kernel(const float* __restrict__ x) {
    int i = (blockIdx.x * 256 + threadIdx.x) * 8;
    float4 a = *(const float4*)(x + i);
    float4 b = *(const float4*)(x + i + 4);
    float v[8] = {a.x, a.y, a.z, a.w, b.x, b.y, b.z, b.w};
    __align__(16) __nv_bfloat16 hi[8];
    __align__(16) __nv_bfloat16 lo[8];
#pragma unroll
    for (int j = 0; j < 8; j++) {
        hi[j] = __float2bfloat16(v[j]);
        lo[j] = __float2bfloat16(v[j] - __bfloat162float(hi[j]));
    }
    *(uint4*)&g_Xh[i] = *(uint4*)hi;
    *(uint4*)&g_Xl[i] = *(uint4*)lo;
}

// ---------------------------------------------------------------------------
// transpose + hi/lo split of W[K=1024, N] -> Wt[N, 1024]
// ---------------------------------------------------------------------------
template <int WSEL>
__global__ __launch_bounds__(256) void wconv_kernel(const float* __restrict__ W) {
    const int Ncols = (WSEL == 0) ? N_QKV : DD;
    __nv_bfloat16* Wh = (WSEL == 0) ? g_Wqh : g_Woh;
    __nv_bfloat16* Wl = (WSEL == 0) ? g_Wql : g_Wol;

    __shared__ float ts[32][33];
    const int n0 = blockIdx.x * 32;
    const int k0 = blockIdx.y * 32;
    const int tx = threadIdx.x & 31;
    const int ty = threadIdx.x >> 5;
#pragma unroll
    for (int i = 0; i < 32; i += 8)
        ts[ty + i][tx] = W[(size_t)(k0 + ty + i) * Ncols + n0 + tx];
    __syncthreads();
#pragma unroll
    for (int i = 0; i < 32; i += 8) {
        float v = ts[tx][ty + i];
        __nv_bfloat16 h = __float2bfloat16(v);
        __nv_bfloat16 l = __float2bfloat16(v - __bfloat162float(h));
        size_t idx = (size_t)(n0 + ty + i) * GK + k0 + tx;
        Wh[idx] = h;
        Wl[idx] = l;
    }
}

// ---------------------------------------------------------------------------
// bf16x3 GEMM with ldmatrix + cp.async double buffering.
// C[128x128 tile] = A @ B^T (+bias)
// MODE 0: A=X, B=Wqkv^T -> scatter bf16 hi/lo Q(scaled)/K/V [B,H,T,HD]
// MODE 1: A=Y, B=Wout^T -> fp32 Cout[m*DD+n]
// ---------------------------------------------------------------------------
#define BK 32
#define LDT 40                                  // padded row (elems); 80B stride
#define TILE_ELEMS (128 * LDT)                  // 5120 elems = 10240 B per tile
#define STAGE_BYTES (4 * TILE_ELEMS * 2)        // 40960 B
#define NKT (GK / BK)                           // 32

template <int MODE>
__global__ __launch_bounds__(256) void mm_gemm_kernel(
    const float* __restrict__ bias,
    float* __restrict__ Cout) {
    extern __shared__ __align__(16) char dsm[];

    const int tid = threadIdx.x;
    const int wid = tid >> 5;
    const int lane = tid & 31;
    const int g = lane >> 2;
    const int t = lane & 3;
    const int warp_m = wid >> 1;
    const int warp_n = wid & 1;
    const int m0 = blockIdx.y * 128;
    const int n0 = blockIdx.x * 128;

    const __nv_bfloat16* ahg = ((MODE == 0) ? g_Xh : g_Yh) + (size_t)m0 * GK;
    const __nv_bfloat16* alg = ((MODE == 0) ? g_Xl : g_Yl) + (size_t)m0 * GK;
    const __nv_bfloat16* bhg = ((MODE == 0) ? g_Wqh : g_Woh) + (size_t)n0 * GK;
    const __nv_bfloat16* blg = ((MODE == 0) ? g_Wql : g_Wol) + (size_t)n0 * GK;

    const uint32_t sb0 = smem_u32(dsm);
    // per-thread gmem/smem offsets for the stage loader (8 x cp16 per stage)
    const int lrow0 = tid >> 2;            // e = tid: rows 0..63
    const int lc0 = tid & 3;
    const int lrow1 = (tid + 256) >> 2;    // rows 64..127
    const int lc1 = lc0;

    // ldmatrix per-lane address components
    const int a_row = (lane & 7) + ((lane >> 3) & 1) * 8;
    const int a_k   = ((lane >> 4) & 1) * 8;
    const int b_row = (lane & 7) + ((lane >> 4) & 1) * 8;
    const int b_k   = ((lane >> 3) & 1) * 8;

    float acc[2][8][4];
#pragma unroll
    for (int i = 0; i < 2; i++)
#pragma unroll
        for (int j = 0; j < 8; j++)
#pragma unroll
            for (int c = 0; c < 4; c++) acc[i][j][c] = 0.f;

    // stage loader
    auto load_stage = [&](int buf, int kt) {
        uint32_t s = sb0 + buf * STAGE_BYTES;
        size_t g0 = (size_t)lrow0 * GK + kt * BK + lc0 * 8;
        size_t g1 = (size_t)lrow1 * GK + kt * BK + lc1 * 8;
        uint32_t o0 = (lrow0 * LDT + lc0 * 8) * 2;
        uint32_t o1 = (lrow1 * LDT + lc1 * 8) * 2;
        cp16(s + o0,                     ahg + g0);
        cp16(s + o1,                     ahg + g1);
        cp16(s + 10240 + o0,             alg + g0);
        cp16(s + 10240 + o1,             alg + g1);
        cp16(s + 20480 + o0,             bhg + g0);
        cp16(s + 20480 + o1,             bhg + g1);
        cp16(s + 30720 + o0,             blg + g0);
        cp16(s + 30720 + o1,             blg + g1);
        CP_COMMIT();
    };

    load_stage(0, 0);

    for (int kt = 0; kt < NKT; ++kt) {
        const int buf = kt & 1;
        if (kt + 1 < NKT) {
            load_stage(buf ^ 1, kt + 1);
            CP_WAIT(1);
        } else {
            CP_WAIT(0);
        }
        __syncthreads();

        const uint32_t s = sb0 + buf * STAGE_BYTES;
        const uint32_t aA = s + ((warp_m * 32 + a_row) * LDT + a_k) * 2;
        const uint32_t bB = s + 20480 + ((warp_n * 64 + b_row) * LDT + b_k) * 2;

#pragma unroll
        for (int ks = 0; ks < BK; ks += 16) {
            uint32_t ah[2][4], al[2][4];
            ldsm_x4(ah[0], aA + ks * 2);
            ldsm_x4(ah[1], aA + (16 * LDT + ks) * 2);
            ldsm_x4(al[0], aA + 10240 + ks * 2);
            ldsm_x4(al[1], aA + 10240 + (16 * LDT + ks) * 2);
            uint32_t Bh[4][4], Bl[4][4];
#pragma unroll
            for (int j = 0; j < 4; j++) {
                ldsm_x4(Bh[j], bB + (j * 16 * LDT + ks) * 2);
                ldsm_x4(Bl[j], bB + 10240 + (j * 16 * LDT + ks) * 2);
            }
#pragma unroll
            for (int nt = 0; nt < 8; nt++) {
                const uint32_t* bh = &Bh[nt >> 1][(nt & 1) * 2];
                const uint32_t* bl = &Bl[nt >> 1][(nt & 1) * 2];
#pragma unroll
                for (int mt = 0; mt < 2; mt++) {
                    mma_bf16(acc[mt][nt], ah[mt], bh);
                    mma_bf16(acc[mt][nt], ah[mt], bl);
                    mma_bf16(acc[mt][nt], al[mt], bh);
                }
            }
        }
        __syncthreads();
    }

    // Epilogue staged through smem (reuses stage memory)
    float* epi = (float*)dsm;   // 128 x 68 fp32 = 34816 B
#pragma unroll
    for (int hf = 0; hf < 2; ++hf) {
        if (warp_n == hf) {
#pragma unroll
            for (int mt = 0; mt < 2; mt++)
#pragma unroll
                for (int nt = 0; nt < 8; nt++) {
                    int row = warp_m * 32 + mt * 16 + g;
                    int col = nt * 8 + 2 * t;
                    epi[row * 68 + col]           = acc[mt][nt][0];
                    epi[row * 68 + col + 1]       = acc[mt][nt][1];
                    epi[(row + 8) * 68 + col]     = acc[mt][nt][2];
                    epi[(row + 8) * 68 + col + 1] = acc[mt][nt][3];
                }
        }
        __syncthreads();
#pragma unroll
        for (int r = 0; r < 8; ++r) {
            int e = tid + 256 * r;
            int row = e >> 4, c4 = e & 15;
            int n = n0 + hf * 64 + c4 * 4;
            float vv[4];
#pragma unroll
            for (int j = 0; j < 4; j++)
                vv[j] = epi[row * 68 + c4 * 4 + j] + bias[n + j];
            int m = m0 + row;
            if (MODE == 0) {
                int b = m >> 11, tt_ = m & 2047;
                int three = n >> 10;
                int h = (n >> 6) & 15;
                int hd = n & 63;
                if (three == 0) {
#pragma unroll
                    for (int j = 0; j < 4; j++) vv[j] *= 0.125f;  // HD^-0.5
                }
                __nv_bfloat16* dsth = (three == 0) ? g_Qh : (three == 1) ? g_Kh : g_Vh;
                __nv_bfloat16* dstl = (three == 0) ? g_Ql : (three == 1) ? g_Kl : g_Vl;
                size_t idx = ((size_t)(b * HH + h) * TT + tt_) * HDIM + hd;
                uint32_t h01, l01, h23, l23;
                h01 = split_bf16x2(vv[0], vv[1], l01);
                h23 = split_bf16x2(vv[2], vv[3], l23);
                uint2 ph = {h01, h23}, pl = {l01, l23};
                *(uint2*)&dsth[idx] = ph;
                *(uint2*)&dstl[idx] = pl;
            } else {
                float4 v = {vv[0], vv[1], vv[2], vv[3]};
                *(float4*)&Cout[(size_t)m * DD + n] = v;
            }
        }
        __syncthreads();
    }
}

// ---------------------------------------------------------------------------
// V transpose: g_Vh/g_Vl [B,H,T,HD] -> g_Vth/g_Vtl [B,H,HD,T]
// ---------------------------------------------------------------------------
__global__ __launch_bounds__(256) void vtrans_kernel() {
    __shared__ __nv_bfloat16 sTh[64][72];
    __shared__ __nv_bfloat16 sTl[64][72];
    const int tid = threadIdx.x;
    const int t0 = blockIdx.x * 64;
    const int bh = blockIdx.y;
    const __nv_bfloat16* Vh = g_Vh + (size_t)bh * TT * HDIM;
    const __nv_bfloat16* Vl = g_Vl + (size_t)bh * TT * HDIM;
#pragma unroll
    for (int r = 0; r < 2; ++r) {
        int e = tid + 256 * r;
        int row = e >> 3, c = e & 7;
        __align__(16) __nv_bfloat16 vh[8], vl[8];
        *(uint4*)vh = *(const uint4*)&Vh[(size_t)(t0 + row) * HDIM + c * 8];
        *(uint4*)vl = *(const uint4*)&Vl[(size_t)(t0 + row) * HDIM + c * 8];
#pragma unroll
        for (int j = 0; j < 8; j++) {
            sTh[c * 8 + j][row] = vh[j];
            sTl[c * 8 + j][row] = vl[j];
        }
    }
    __syncthreads();
#pragma unroll
    for (int r = 0; r < 2; ++r) {
        int e = tid + 256 * r;
        int hd = e >> 3, c = e & 7;
        size_t idx = (size_t)bh * HDIM * TT + (size_t)hd * TT + t0 + c * 8;
        *(uint4*)&g_Vth[idx] = *(uint4*)&sTh[hd][c * 8];
        *(uint4*)&g_Vtl[idx] = *(uint4*)&sTl[hd][c * 8];
    }
}

// ---------------------------------------------------------------------------
// Flash attention on tensor cores (bf16x3), causal. 128 q-rows x 8 warps.
// ---------------------------------------------------------------------------
__global__ __launch_bounds__(256, 1) void fattn_kernel() {
    __shared__ __nv_bfloat16 sKh[64][72];
    __shared__ __nv_bfloat16 sKl[64][72];
    __shared__ __nv_bfloat16 sVh[64][72];   // V^T tile: [hd][key]
    __shared__ __nv_bfloat16 sVl[64][72];

    const int tid = threadIdx.x;
    const int wid = tid >> 5;
    const int lane = tid & 31;
    const int g = lane >> 2;
    const int t = lane & 3;
    const int qt = gridDim.x - 1 - blockIdx.x;
    const int bh = blockIdx.y;

    const int row0 = qt * 128 + wid * 16 + g;
    const __nv_bfloat16* Qh = g_Qh + (size_t)bh * TT * HDIM;
    const __nv_bfloat16* Ql = g_Ql + (size_t)bh * TT * HDIM;
    const __nv_bfloat16* Kh = g_Kh + (size_t)bh * TT * HDIM;
    const __nv_bfloat16* Kl = g_Kl + (size_t)bh * TT * HDIM;
    const __nv_bfloat16* Vth = g_Vth + (size_t)bh * HDIM * TT;
    const __nv_bfloat16* Vtl = g_Vtl + (size_t)bh * HDIM * TT;

    uint32_t qh[4][4], ql[4][4];
#pragma unroll
    for (int kk = 0; kk < 4; kk++) {
        const __nv_bfloat16* p = Qh + (size_t)row0 * HDIM + kk * 16 + 2 * t;
        qh[kk][0] = *(const uint32_t*)p;
        qh[kk][1] = *(const uint32_t*)(p + 8 * HDIM);
        qh[kk][2] = *(const uint32_t*)(p + 8);
        qh[kk][3] = *(const uint32_t*)(p + 8 * HDIM + 8);
        const __nv_bfloat16* pl = Ql + (size_t)row0 * HDIM + kk * 16 + 2 * t;
        ql[kk][0] = *(const uint32_t*)pl;
        ql[kk][1] = *(const uint32_t*)(pl + 8 * HDIM);
        ql[kk][2] = *(const uint32_t*)(pl + 8);
        ql[kk][3] = *(const uint32_t*)(pl + 8 * HDIM + 8);
    }

    float o[8][4];
#pragma unroll
    for (int nt = 0; nt < 8; nt++)
#pragma unroll
        for (int c = 0; c < 4; c++) o[nt][c] = 0.f;
    float mi[2] = {-1e30f, -1e30f};
    float li[2] = {0.f, 0.f};

    const int nkt = 2 * qt + 2;
    const int warp_max_row = qt * 128 + wid * 16 + 15;

    for (int kt = 0; kt < nkt; ++kt) {
        __syncthreads();
#pragma unroll
        for (int r = 0; r < 2; ++r) {
            int e = tid + 256 * r;
            int row = e >> 3, c = e & 7;
            size_t kofs = (size_t)(kt * 64 + row) * HDIM + c * 8;
            *(uint4*)&sKh[row][c * 8] = *(const uint4*)&Kh[kofs];
            *(uint4*)&sKl[row][c * 8] = *(const uint4*)&Kl[kofs];
            size_t vofs = (size_t)row * TT + kt * 64 + c * 8;
            *(uint4*)&sVh[row][c * 8] = *(const uint4*)&Vth[vofs];
            *(uint4*)&sVl[row][c * 8] = *(const uint4*)&Vtl[vofs];
        }
        __syncthreads();

        if (kt * 64 > warp_max_row) continue;

        float s[8][4];
#pragma unroll
        for (int nt = 0; nt < 8; nt++)
#pragma unroll
            for (int c = 0; c < 4; c++) s[nt][c] = 0.f;
#pragma unroll
        for (int kk = 0; kk < 4; kk++) {
#pragma unroll
            for (int nt = 0; nt < 8; nt++) {
                uint32_t bhf[2], blf[2];
                const __nv_bfloat16* pB = &sKh[nt * 8 + g][kk * 16 + 2 * t];
                bhf[0] = *(const uint32_t*)pB;
                bhf[1] = *(const uint32_t*)(pB + 8);
                const __nv_bfloat16* pBl = &sKl[nt * 8 + g][kk * 16 + 2 * t];
                blf[0] = *(const uint32_t*)pBl;
                blf[1] = *(const uint32_t*)(pBl + 8);
                mma_bf16(s[nt], qh[kk], bhf);
                mma_bf16(s[nt], qh[kk], blf);
                mma_bf16(s[nt], ql[kk], bhf);
            }
        }

        if (kt >= 2 * qt) {
#pragma unroll
            for (int nt = 0; nt < 8; nt++) {
#pragma unroll
                for (int c = 0; c < 4; c++) {
                    int col = kt * 64 + nt * 8 + 2 * t + (c & 1);
                    int row = row0 + ((c >> 1) << 3);
                    if (col > row) s[nt][c] = -1e30f;
                }
            }
        }

        float alpha[2];
#pragma unroll
        for (int hf = 0; hf < 2; hf++) {
            float pm = -1e30f;
#pragma unroll
            for (int nt = 0; nt < 8; nt++)
                pm = fmaxf(pm, fmaxf(s[nt][hf * 2], s[nt][hf * 2 + 1]));
            pm = fmaxf(pm, __shfl_xor_sync(0xffffffffu, pm, 1));
            pm = fmaxf(pm, __shfl_xor_sync(0xffffffffu, pm, 2));
            float mn = fmaxf(mi[hf], pm);
            alpha[hf] = __expf(mi[hf] - mn);
            float ps = 0.f;
#pragma unroll
            for (int nt = 0; nt < 8; nt++) {
                s[nt][hf * 2]     = __expf(s[nt][hf * 2] - mn);
                s[nt][hf * 2 + 1] = __expf(s[nt][hf * 2 + 1] - mn);
                ps += s[nt][hf * 2] + s[nt][hf * 2 + 1];
            }
            ps += __shfl_xor_sync(0xffffffffu, ps, 1);
            ps += __shfl_xor_sync(0xffffffffu, ps, 2);
            li[hf] = li[hf] * alpha[hf] + ps;
            mi[hf] = mn;
        }
#pragma unroll
        for (int nt = 0; nt < 8; nt++) {
            o[nt][0] *= alpha[0];
            o[nt][1] *= alpha[0];
            o[nt][2] *= alpha[1];
            o[nt][3] *= alpha[1];
        }

#pragma unroll
        for (int kk2 = 0; kk2 < 4; kk2++) {
            uint32_t ph[4], plo[4];
            ph[0] = split_bf16x2(s[2 * kk2][0],     s[2 * kk2][1],     plo[0]);
            ph[1] = split_bf16x2(s[2 * kk2][2],     s[2 * kk2][3],     plo[1]);
            ph[2] = split_bf16x2(s[2 * kk2 + 1][0], s[2 * kk2 + 1][1], plo[2]);
            ph[3] = split_bf16x2(s[2 * kk2 + 1][2], s[2 * kk2 + 1][3], plo[3]);
#pragma unroll
            for (int nt = 0; nt < 8; nt++) {
                uint32_t vhf[2], vlf[2];
                const __nv_bfloat16* pV = &sVh[nt * 8 + g][kk2 * 16 + 2 * t];
                vhf[0] = *(const uint32_t*)pV;
                vhf[1] = *(const uint32_t*)(pV + 8);
                const __nv_bfloat16* pVl = &sVl[nt * 8 + g][kk2 * 16 + 2 * t];
                vlf[0] = *(const uint32_t*)pVl;
                vlf[1] = *(const uint32_t*)(pVl + 8);
                mma_bf16(o[nt], ph, vhf);
                mma_bf16(o[nt], ph, vlf);
                mma_bf16(o[nt], plo, vhf);
            }
        }
    }

    const float inv0 = 1.f / li[0];
    const float inv1 = 1.f / li[1];
    const int b = bh >> 4;
    const int h = bh & 15;
    size_t base0 = ((size_t)(b * TT + row0)) * DD + h * 64;
    size_t base1 = base0 + (size_t)8 * DD;
#pragma unroll
    for (int nt = 0; nt < 8; nt++) {
        int col = nt * 8 + 2 * t;
        uint32_t l0, l1;
        uint32_t h0 = split_bf16x2(o[nt][0] * inv0, o[nt][1] * inv0, l0);
        uint32_t h1 = split_bf16x2(o[nt][2] * inv1, o[nt][3] * inv1, l1);
        *(uint32_t*)&g_Yh[base0 + col] = h0;
        *(uint32_t*)&g_Yl[base0 + col] = l0;
        *(uint32_t*)&g_Yh[base1 + col] = h1;
        *(uint32_t*)&g_Yl[base1 + col] = l1;
    }
}

// ---------------------------------------------------------------------------
extern "C" void kernel_launch(void* const* d_in, const int* in_sizes, int n_in,
                              void* d_out, int out_size) {
    const float* x    = (const float*)d_in[0];
    const float* Wqkv = (const float*)d_in[1];
    const float* bqkv = (const float*)d_in[2];
    const float* Wout = (const float*)d_in[3];
    const float* bout = (const float*)d_in[4];
    float* out = (float*)d_out;

    const int SMEM = 2 * STAGE_BYTES;   // 81920
    cudaFuncSetAttribute(mm_gemm_kernel<0>,
                         cudaFuncAttributeMaxDynamicSharedMemorySize, SMEM);
    cudaFuncSetAttribute(mm_gemm_kernel<1>,
                         cudaFuncAttributeMaxDynamicSharedMemorySize, SMEM);

    // 1) conversions
    xconv_kernel<<<MROWS * DD / (256 * 8), 256>>>(x);
    wconv_kernel<0><<<dim3(N_QKV / 32, GK / 32), 256>>>(Wqkv);
    wconv_kernel<1><<<dim3(DD / 32, GK / 32), 256>>>(Wout);

    // 2) QKV projection (bf16x3 mma + ldmatrix + cp.async)
    mm_gemm_kernel<0><<<dim3(N_QKV / 128, MROWS / 128), 256, SMEM>>>(bqkv, nullptr);

    // 3) V transpose
    vtrans_kernel<<<dim3(TT / 64, BB * HH), 256>>>();

    // 4) causal flash attention on tensor cores
    fattn_kernel<<<dim3(TT / 128, BB * HH), 256>>>();

    // 5) output projection
    mm_gemm_kernel<1><<<dim3(DD / 128, MROWS / 128), 256, SMEM>>>(bout, out);
}